// round 16
// baseline (speedup 1.0000x reference)
#include <cuda_runtime.h>
#include <cstdint>

#define F_ 256
#define T_ 128
#define D_ 6
#define U_ 16
#define NB_ 64
#define N_ 768          // T_*D_
#define BROWS 32        // batch rows per CTA
#define CCOLS 192       // 32 trees * 6 cols per chunk
#define NPAIR 96        // col-pairs per chunk
#define NCHUNK 4
#define THREADS 512
#define SEL_LD 128      // sel tile row stride (floats) — R10-proven config
#define P_LD 197        // padded row stride for p tile (odd -> conflict-free rows)
#define XT_LD 36        // padded row stride for transposed x (floats, mult of 4)

// Selector after sparsemax, PAIR-PACKED: g_sel_p[(jp*F_ + f)*2 + (d&1)],
// jp = t*3 + d/2. One jp row = 512 contiguous floats (pairs for all f).
__device__ float g_sel_p[(N_ / 2) * F_ * 2];

typedef unsigned long long u64;

__device__ __forceinline__ float f4get(const float4& v, int i) {
    return i == 0 ? v.x : (i == 1 ? v.y : (i == 2 ? v.z : v.w));
}
__device__ __forceinline__ u64 pk(float lo, float hi) {
    u64 r; asm("mov.b64 %0, {%1, %2};" : "=l"(r) : "f"(lo), "f"(hi)); return r;
}
__device__ __forceinline__ u64 pkdup(float v) { return pk(v, v); }
__device__ __forceinline__ u64 mul2(u64 a, u64 b) {
    u64 d; asm("mul.rn.f32x2 %0, %1, %2;" : "=l"(d) : "l"(a), "l"(b)); return d;
}
__device__ __forceinline__ u64 fma2(u64 a, u64 b, u64 c) {
    u64 d; asm("fma.rn.f32x2 %0, %1, %2, %3;" : "=l"(d) : "l"(a), "l"(b), "l"(c)); return d;
}
__device__ __forceinline__ float lo32(u64 v) { return __uint_as_float((unsigned)(v & 0xffffffffull)); }
__device__ __forceinline__ float hi32(u64 v) { return __uint_as_float((unsigned)(v >> 32)); }

__device__ __forceinline__ uint32_t smem_u32(const void* p) {
    uint32_t a;
    asm("{ .reg .u64 t; cvta.to.shared.u64 t, %1; cvt.u32.u64 %0, t; }"
        : "=r"(a) : "l"(p));
    return a;
}
__device__ __forceinline__ void cpa16(uint32_t dst, const float* src) {
    asm volatile("cp.async.cg.shared.global [%0], [%1], 16;" :: "r"(dst), "l"(src));
}
#define CP_COMMIT() asm volatile("cp.async.commit_group;" ::: "memory")
#define CP_WAIT0()  asm volatile("cp.async.wait_group 0;" ::: "memory")

// ---------------------------------------------------------------------------
// Kernel 1: sparsemax over last axis (D=6); writes pair-packed selector.
// ---------------------------------------------------------------------------
__global__ __launch_bounds__(256) void sparsemax_kernel(const float* __restrict__ fsl) {
    int idx = blockIdx.x * blockDim.x + threadIdx.x;   // 0 .. F_*T_-1
    if (idx >= F_ * T_) return;
    const int f = idx >> 7;
    const int t = idx & (T_ - 1);
    const float* zin = fsl + (size_t)idx * D_;
    float z[D_], zs[D_];
#pragma unroll
    for (int d = 0; d < D_; d++) { z[d] = zin[d]; zs[d] = z[d]; }
#pragma unroll
    for (int i = 0; i < D_; i++) {
#pragma unroll
        for (int j = 0; j < D_ - 1; j++) {
            if (zs[j] < zs[j + 1]) { float tt = zs[j]; zs[j] = zs[j + 1]; zs[j + 1] = tt; }
        }
    }
    float csum[D_];
    float cs = 0.0f;
#pragma unroll
    for (int k = 0; k < D_; k++) { cs += zs[k]; csum[k] = cs; }
    int kz = 0;
#pragma unroll
    for (int k = 0; k < D_; k++) {
        if (1.0f + (float)(k + 1) * zs[k] > csum[k]) kz++;
    }
    float tau = (csum[kz - 1] - 1.0f) / (float)kz;
#pragma unroll
    for (int d = 0; d < D_; d++) {
        int jp = t * 3 + (d >> 1);
        g_sel_p[((size_t)jp * F_ + f) * 2 + (d & 1)] = fmaxf(z[d] - tau, 0.0f);
    }
}

// ---------------------------------------------------------------------------
// Kernel 2: fused feature GEMM + sparsemoid + tree eval + response contraction.
// R10 configuration (proven 92.3us) with GEMM kq loop unrolled 8 deep.
// ---------------------------------------------------------------------------
__global__ __launch_bounds__(THREADS, 1) void odst_main(
    const float* __restrict__ x,
    const float* __restrict__ thr,
    const float* __restrict__ lt,
    const float* __restrict__ resp,
    float* __restrict__ out)
{
    extern __shared__ float smem[];
    float* x_t    = smem;                        // [256][XT_LD]     9216 f
    float* sel0   = x_t + 256 * XT_LD;           // [96][SEL_LD]    12288 f
    float* sel1   = sel0 + NPAIR * SEL_LD;       // [96][SEL_LD]    12288 f
    float* p_s    = sel1 + NPAIR * SEL_LD;       // [32][P_LD]       6304 f
    float* a_s    = p_s + 32 * P_LD;             // [192]
    float* b_s    = a_s + CCOLS;                 // [192]
    float* out_s  = b_s + CCOLS;                 // [32][16]          512 f

    const int tid  = threadIdx.x;
    const int row0 = blockIdx.x * BROWS;

    const uint32_t sel_u32[2] = { smem_u32(sel0), smem_u32(sel1) };

    out_s[tid] = 0.0f;

    // ---- load x tile TRANSPOSED: x_t[c][row], c=0..255, row=0..31 ----
    {
        const int c   = tid & 255;
        const int r0t = (tid >> 8) * 16;     // 0 or 16
        float tmp[16];
#pragma unroll
        for (int i = 0; i < 16; i++)
            tmp[i] = __ldg(&x[(size_t)(row0 + r0t + i) * F_ + c]);
#pragma unroll
        for (int i = 0; i < 4; i++) {
            float4 v = make_float4(tmp[4 * i], tmp[4 * i + 1],
                                   tmp[4 * i + 2], tmp[4 * i + 3]);
            *(float4*)&x_t[c * XT_LD + r0t + i * 4] = v;
        }
    }

    const int w    = tid >> 5;          // 0..15
    const int lane = tid & 31;

    // eval-phase decomposition
    const int rb   = (lane & 7) * 4;    // row base (4 rows)
    const int ub   = (lane >> 3) * 4;   // u base (4 outputs)

    // GEMM-phase decomposition: 2 rows x 6 cols (3 col-pairs) per thread
    const int rowg = tid & 15;
    const int colg = tid >> 4;          // 0..31
    const int r0g  = rowg * 2;
    const int c0   = colg * 6;
    const int jp0  = colg * 3;          // first col-pair index

    u64 accp[2][4];
#pragma unroll
    for (int pr = 0; pr < 2; pr++)
#pragma unroll
        for (int uu = 0; uu < 4; uu++) accp[pr][uu] = 0ull;

    for (int chunk = 0; chunk < NCHUNK; chunk++) {
        const int nbase  = chunk * CCOLS;
        const int pbase  = chunk * NPAIR;    // first jp of chunk
        __syncthreads();  // prev chunk eval done (p_s, sel bufs free); x_t ready

        // ---- issue cp.async for kb=0 tile into sel0 ----
#pragma unroll
        for (int p = 0; p < 6; p++) {
            int c  = tid + p * 512;          // 0..3071
            int jp = c >> 5;
            int co = (c & 31) * 4;           // float offset in 128-float slice
            const float* src = g_sel_p + ((size_t)(pbase + jp) * F_) * 2 + co;
            cpa16(sel_u32[0] + (uint32_t)(jp * SEL_LD + co) * 4u, src);
        }
        CP_COMMIT();

        if (tid < CCOLS) {
            float e = 0.5f * expf(-lt[nbase + tid]);
            a_s[tid] = e;
            b_s[tid] = 0.5f - e * thr[nbase + tid];
        }

        CP_WAIT0();
        __syncthreads();

        // packed GEMM accumulators: 2 rows x 3 col-pairs
        u64 fvA[3], fvB[3];
#pragma unroll
        for (int j = 0; j < 3; j++) { fvA[j] = 0ull; fvB[j] = 0ull; }

        for (int kb = 0; kb < 4; kb++) {
            const float* cur = (kb & 1) ? sel1 : sel0;
            const uint32_t nxt_u32 = sel_u32[(kb + 1) & 1];

            // issue async copy of next tile (in flight during compute)
            if (kb < 3) {
#pragma unroll
                for (int p = 0; p < 6; p++) {
                    int c  = tid + p * 512;
                    int jp = c >> 5;
                    int co = (c & 31) * 4;
                    const float* src = g_sel_p
                        + ((size_t)(pbase + jp) * F_ + (kb + 1) * 64) * 2 + co;
                    cpa16(nxt_u32 + (uint32_t)(jp * SEL_LD + co) * 4u, src);
                }
                CP_COMMIT();
            }

            // compute on current tile: 16 iterations of 4 k-steps (unroll 8)
            const float* selc = cur + jp0 * SEL_LD;
            const float* xb0  = x_t + (kb * 64) * XT_LD + r0g;
#pragma unroll 8
            for (int kq = 0; kq < 16; kq++) {
                const int kbase = kq * 8;
                ulonglong2 q0a = *(const ulonglong2*)(selc + kbase);
                ulonglong2 q0b = *(const ulonglong2*)(selc + kbase + 4);
                ulonglong2 q1a = *(const ulonglong2*)(selc + SEL_LD + kbase);
                ulonglong2 q1b = *(const ulonglong2*)(selc + SEL_LD + kbase + 4);
                ulonglong2 q2a = *(const ulonglong2*)(selc + 2 * SEL_LD + kbase);
                ulonglong2 q2b = *(const ulonglong2*)(selc + 2 * SEL_LD + kbase + 4);
                const float* xk = xb0 + (kq * 4) * XT_LD;
                float2 x0 = *(const float2*)(xk);
                float2 x1 = *(const float2*)(xk + XT_LD);
                float2 x2 = *(const float2*)(xk + 2 * XT_LD);
                float2 x3 = *(const float2*)(xk + 3 * XT_LD);

                u64 xa, xb;
                xa = pkdup(x0.x); xb = pkdup(x0.y);
                fvA[0] = fma2(xa, q0a.x, fvA[0]);
                fvA[1] = fma2(xa, q1a.x, fvA[1]);
                fvA[2] = fma2(xa, q2a.x, fvA[2]);
                fvB[0] = fma2(xb, q0a.x, fvB[0]);
                fvB[1] = fma2(xb, q1a.x, fvB[1]);
                fvB[2] = fma2(xb, q2a.x, fvB[2]);
                xa = pkdup(x1.x); xb = pkdup(x1.y);
                fvA[0] = fma2(xa, q0a.y, fvA[0]);
                fvA[1] = fma2(xa, q1a.y, fvA[1]);
                fvA[2] = fma2(xa, q2a.y, fvA[2]);
                fvB[0] = fma2(xb, q0a.y, fvB[0]);
                fvB[1] = fma2(xb, q1a.y, fvB[1]);
                fvB[2] = fma2(xb, q2a.y, fvB[2]);
                xa = pkdup(x2.x); xb = pkdup(x2.y);
                fvA[0] = fma2(xa, q0b.x, fvA[0]);
                fvA[1] = fma2(xa, q1b.x, fvA[1]);
                fvA[2] = fma2(xa, q2b.x, fvA[2]);
                fvB[0] = fma2(xb, q0b.x, fvB[0]);
                fvB[1] = fma2(xb, q1b.x, fvB[1]);
                fvB[2] = fma2(xb, q2b.x, fvB[2]);
                xa = pkdup(x3.x); xb = pkdup(x3.y);
                fvA[0] = fma2(xa, q0b.y, fvA[0]);
                fvA[1] = fma2(xa, q1b.y, fvA[1]);
                fvA[2] = fma2(xa, q2b.y, fvA[2]);
                fvB[0] = fma2(xb, q0b.y, fvB[0]);
                fvB[1] = fma2(xb, q1b.y, fvB[1]);
                fvB[2] = fma2(xb, q2b.y, fvB[2]);
            }

            if (kb < 3) {
                CP_WAIT0();      // next tile landed (issued before compute)
                __syncthreads();
            }
        }

        // sparsemoid: p = saturate(a*fv + b); rows r0g..r0g+1, cols c0..c0+5
#pragma unroll
        for (int j = 0; j < 3; j++) {
            int cc = c0 + 2 * j;
            float fa0 = lo32(fvA[j]), fa1 = hi32(fvA[j]);
            float fb0 = lo32(fvB[j]), fb1 = hi32(fvB[j]);
            p_s[r0g * P_LD + cc]           = __saturatef(fmaf(a_s[cc],     fa0, b_s[cc]));
            p_s[r0g * P_LD + cc + 1]       = __saturatef(fmaf(a_s[cc + 1], fa1, b_s[cc + 1]));
            p_s[(r0g + 1) * P_LD + cc]     = __saturatef(fmaf(a_s[cc],     fb0, b_s[cc]));
            p_s[(r0g + 1) * P_LD + cc + 1] = __saturatef(fmaf(a_s[cc + 1], fb1, b_s[cc + 1]));
        }
        __syncthreads();

        // ---- tree eval: warp w handles trees chunk*32 + {w, w+16} ----
        for (int it = 0; it < 2; it++) {
            const int tloc = it * 16 + w;
            const int tg   = chunk * 32 + tloc;
            const float4* rg = (const float4*)(resp + (size_t)tg * (U_ * NB_));

            const int pc = tloc * 6;
            u64 r01p[2][4], r23p[2][4], r45p[2][4];
#pragma unroll
            for (int pr = 0; pr < 2; pr++) {
                const float* prow0 = p_s + (rb + 2 * pr) * P_LD + pc;
                const float* prow1 = prow0 + P_LD;
                u64 P0 = pk(prow0[0], prow1[0]);
                u64 P1 = pk(prow0[1], prow1[1]);
                u64 P2 = pk(prow0[2], prow1[2]);
                u64 P3 = pk(prow0[3], prow1[3]);
                u64 P4 = pk(prow0[4], prow1[4]);
                u64 P5 = pk(prow0[5], prow1[5]);
                const u64 ONE = 0x3f8000003f800000ull;
                const u64 NEG = 0xbf800000bf800000ull;
                u64 Q0 = fma2(P0, NEG, ONE);
                u64 Q1 = fma2(P1, NEG, ONE);
                u64 Q2 = fma2(P2, NEG, ONE);
                u64 Q3 = fma2(P3, NEG, ONE);
                u64 Q4 = fma2(P4, NEG, ONE);
                u64 Q5 = fma2(P5, NEG, ONE);
                r01p[pr][0] = mul2(P0, P1); r01p[pr][1] = mul2(Q0, P1);
                r01p[pr][2] = mul2(P0, Q1); r01p[pr][3] = mul2(Q0, Q1);
                r23p[pr][0] = mul2(P2, P3); r23p[pr][1] = mul2(Q2, P3);
                r23p[pr][2] = mul2(P2, Q3); r23p[pr][3] = mul2(Q2, Q3);
                r45p[pr][0] = mul2(P4, P5); r45p[pr][1] = mul2(Q4, P5);
                r45p[pr][2] = mul2(P4, Q5); r45p[pr][3] = mul2(Q4, Q5);
            }

#pragma unroll
            for (int j45 = 0; j45 < 4; j45++) {
#pragma unroll
                for (int j23 = 0; j23 < 4; j23++) {
                    u64 t2p0 = mul2(r45p[0][j45], r23p[0][j23]);
                    u64 t2p1 = mul2(r45p[1][j45], r23p[1][j23]);
                    const int cq = j45 * 4 + j23;
                    float4 rv0 = __ldg(&rg[(ub + 0) * 16 + cq]);
                    float4 rv1 = __ldg(&rg[(ub + 1) * 16 + cq]);
                    float4 rv2 = __ldg(&rg[(ub + 2) * 16 + cq]);
                    float4 rv3 = __ldg(&rg[(ub + 3) * 16 + cq]);
#pragma unroll
                    for (int j01 = 0; j01 < 4; j01++) {
                        u64 rw0 = mul2(t2p0, r01p[0][j01]);
                        u64 rw1 = mul2(t2p1, r01p[1][j01]);
                        u64 e0 = pkdup(f4get(rv0, j01));
                        u64 e1 = pkdup(f4get(rv1, j01));
                        u64 e2 = pkdup(f4get(rv2, j01));
                        u64 e3 = pkdup(f4get(rv3, j01));
                        accp[0][0] = fma2(rw0, e0, accp[0][0]);
                        accp[0][1] = fma2(rw0, e1, accp[0][1]);
                        accp[0][2] = fma2(rw0, e2, accp[0][2]);
                        accp[0][3] = fma2(rw0, e3, accp[0][3]);
                        accp[1][0] = fma2(rw1, e0, accp[1][0]);
                        accp[1][1] = fma2(rw1, e1, accp[1][1]);
                        accp[1][2] = fma2(rw1, e2, accp[1][2]);
                        accp[1][3] = fma2(rw1, e3, accp[1][3]);
                    }
                }
            }
        }
    }

    // unpack accumulators into scalars
    float acc[4][4];
#pragma unroll
    for (int pr = 0; pr < 2; pr++)
#pragma unroll
        for (int uu = 0; uu < 4; uu++) {
            acc[2 * pr + 0][uu] = lo32(accp[pr][uu]);
            acc[2 * pr + 1][uu] = hi32(accp[pr][uu]);
        }

    // deterministic cross-warp reduction into out_s
    for (int pass = 0; pass < 16; pass++) {
        __syncthreads();
        if (w == pass) {
#pragma unroll
            for (int rr = 0; rr < 4; rr++)
#pragma unroll
                for (int uu = 0; uu < 4; uu++)
                    out_s[(rb + rr) * U_ + ub + uu] += acc[rr][uu];
        }
    }
    __syncthreads();

    out[(size_t)row0 * U_ + tid] = out_s[tid];
}

// ---------------------------------------------------------------------------
extern "C" void kernel_launch(void* const* d_in, const int* in_sizes, int n_in,
                              void* d_out, int out_size) {
    const float* x    = (const float*)d_in[0];
    const float* fsl  = (const float*)d_in[1];
    const float* thr  = (const float*)d_in[2];
    const float* lt   = (const float*)d_in[3];
    const float* resp = (const float*)d_in[4];
    float* out = (float*)d_out;

    const int smem_bytes =
        (256 * XT_LD + 2 * NPAIR * SEL_LD + 32 * P_LD + 2 * CCOLS + 512)
        * (int)sizeof(float);   // 163,968 B

    cudaFuncSetAttribute(odst_main, cudaFuncAttributeMaxDynamicSharedMemorySize,
                         smem_bytes);

    sparsemax_kernel<<<(F_ * T_) / 256, 256>>>(fsl);
    odst_main<<<(4096 / BROWS), THREADS, smem_bytes>>>(x, thr, lt, resp, out);
}

// round 17
// speedup vs baseline: 1.6130x; 1.6130x over previous
#include <cuda_runtime.h>
#include <cstdint>

#define F_ 256
#define T_ 128
#define D_ 6
#define U_ 16
#define NB_ 64
#define N_ 768          // T_*D_
#define BROWS 32        // batch rows per CTA
#define CCOLS 192       // 32 trees * 6 cols per chunk
#define NPAIR 96        // col-pairs per chunk
#define NCHUNK 4
#define THREADS 512
#define SEL_LD 128      // sel tile row stride (floats) — R10-proven config
#define P_LD 197        // padded row stride for p tile (odd -> conflict-free rows)
#define XT_LD 36        // padded row stride for transposed x (floats, mult of 4)

// Selector after sparsemax, PAIR-PACKED: g_sel_p[(jp*F_ + f)*2 + (d&1)],
// jp = t*3 + d/2. One jp row = 512 contiguous floats (pairs for all f).
__device__ float g_sel_p[(N_ / 2) * F_ * 2];

typedef unsigned long long u64;

__device__ __forceinline__ float f4get(const float4& v, int i) {
    return i == 0 ? v.x : (i == 1 ? v.y : (i == 2 ? v.z : v.w));
}
__device__ __forceinline__ u64 pk(float lo, float hi) {
    u64 r; asm("mov.b64 %0, {%1, %2};" : "=l"(r) : "f"(lo), "f"(hi)); return r;
}
__device__ __forceinline__ u64 pkdup(float v) { return pk(v, v); }
__device__ __forceinline__ u64 mul2(u64 a, u64 b) {
    u64 d; asm("mul.rn.f32x2 %0, %1, %2;" : "=l"(d) : "l"(a), "l"(b)); return d;
}
__device__ __forceinline__ u64 fma2(u64 a, u64 b, u64 c) {
    u64 d; asm("fma.rn.f32x2 %0, %1, %2, %3;" : "=l"(d) : "l"(a), "l"(b), "l"(c)); return d;
}
__device__ __forceinline__ float lo32(u64 v) { return __uint_as_float((unsigned)(v & 0xffffffffull)); }
__device__ __forceinline__ float hi32(u64 v) { return __uint_as_float((unsigned)(v >> 32)); }

__device__ __forceinline__ uint32_t smem_u32(const void* p) {
    uint32_t a;
    asm("{ .reg .u64 t; cvta.to.shared.u64 t, %1; cvt.u32.u64 %0, t; }"
        : "=r"(a) : "l"(p));
    return a;
}
__device__ __forceinline__ void cpa16(uint32_t dst, const float* src) {
    asm volatile("cp.async.cg.shared.global [%0], [%1], 16;" :: "r"(dst), "l"(src));
}
#define CP_COMMIT() asm volatile("cp.async.commit_group;" ::: "memory")
#define CP_WAIT0()  asm volatile("cp.async.wait_group 0;" ::: "memory")

// ---------------------------------------------------------------------------
// Kernel 1: sparsemax over last axis (D=6); writes pair-packed selector.
// ---------------------------------------------------------------------------
__global__ __launch_bounds__(256) void sparsemax_kernel(const float* __restrict__ fsl) {
    int idx = blockIdx.x * blockDim.x + threadIdx.x;   // 0 .. F_*T_-1
    if (idx >= F_ * T_) return;
    const int f = idx >> 7;
    const int t = idx & (T_ - 1);
    const float* zin = fsl + (size_t)idx * D_;
    float z[D_], zs[D_];
#pragma unroll
    for (int d = 0; d < D_; d++) { z[d] = zin[d]; zs[d] = z[d]; }
#pragma unroll
    for (int i = 0; i < D_; i++) {
#pragma unroll
        for (int j = 0; j < D_ - 1; j++) {
            if (zs[j] < zs[j + 1]) { float tt = zs[j]; zs[j] = zs[j + 1]; zs[j + 1] = tt; }
        }
    }
    float csum[D_];
    float cs = 0.0f;
#pragma unroll
    for (int k = 0; k < D_; k++) { cs += zs[k]; csum[k] = cs; }
    int kz = 0;
#pragma unroll
    for (int k = 0; k < D_; k++) {
        if (1.0f + (float)(k + 1) * zs[k] > csum[k]) kz++;
    }
    float tau = (csum[kz - 1] - 1.0f) / (float)kz;
#pragma unroll
    for (int d = 0; d < D_; d++) {
        int jp = t * 3 + (d >> 1);
        g_sel_p[((size_t)jp * F_ + f) * 2 + (d & 1)] = fmaxf(z[d] - tau, 0.0f);
    }
}

// ---------------------------------------------------------------------------
// Kernel 2: R10-exact hot loops. One change: next chunk's kb=0 selector copy
// is issued during the current chunk's last GEMM tile (sel0 is dead then),
// so its latency hides behind the whole eval phase.
// ---------------------------------------------------------------------------
__global__ __launch_bounds__(THREADS, 1) void odst_main(
    const float* __restrict__ x,
    const float* __restrict__ thr,
    const float* __restrict__ lt,
    const float* __restrict__ resp,
    float* __restrict__ out)
{
    extern __shared__ float smem[];
    float* x_t    = smem;                        // [256][XT_LD]     9216 f
    float* sel0   = x_t + 256 * XT_LD;           // [96][SEL_LD]    12288 f
    float* sel1   = sel0 + NPAIR * SEL_LD;       // [96][SEL_LD]    12288 f
    float* p_s    = sel1 + NPAIR * SEL_LD;       // [32][P_LD]       6304 f
    float* a_s    = p_s + 32 * P_LD;             // [192]
    float* b_s    = a_s + CCOLS;                 // [192]
    float* out_s  = b_s + CCOLS;                 // [32][16]          512 f

    const int tid  = threadIdx.x;
    const int row0 = blockIdx.x * BROWS;

    const uint32_t sel_u32[2] = { smem_u32(sel0), smem_u32(sel1) };

    out_s[tid] = 0.0f;

    // ---- load x tile TRANSPOSED: x_t[c][row], c=0..255, row=0..31 ----
    {
        const int c   = tid & 255;
        const int r0t = (tid >> 8) * 16;     // 0 or 16
        float tmp[16];
#pragma unroll
        for (int i = 0; i < 16; i++)
            tmp[i] = __ldg(&x[(size_t)(row0 + r0t + i) * F_ + c]);
#pragma unroll
        for (int i = 0; i < 4; i++) {
            float4 v = make_float4(tmp[4 * i], tmp[4 * i + 1],
                                   tmp[4 * i + 2], tmp[4 * i + 3]);
            *(float4*)&x_t[c * XT_LD + r0t + i * 4] = v;
        }
    }

    const int w    = tid >> 5;          // 0..15
    const int lane = tid & 31;

    // eval-phase decomposition
    const int rb   = (lane & 7) * 4;    // row base (4 rows)
    const int ub   = (lane >> 3) * 4;   // u base (4 outputs)

    // GEMM-phase decomposition: 2 rows x 6 cols (3 col-pairs) per thread
    const int rowg = tid & 15;
    const int colg = tid >> 4;          // 0..31
    const int r0g  = rowg * 2;
    const int c0   = colg * 6;
    const int jp0  = colg * 3;          // first col-pair index

    u64 accp[2][4];
#pragma unroll
    for (int pr = 0; pr < 2; pr++)
#pragma unroll
        for (int uu = 0; uu < 4; uu++) accp[pr][uu] = 0ull;

    for (int chunk = 0; chunk < NCHUNK; chunk++) {
        const int nbase  = chunk * CCOLS;
        const int pbase  = chunk * NPAIR;    // first jp of chunk
        __syncthreads();  // prev chunk eval done (p_s, sel bufs free); x_t ready

        // chunk 0: issue its kb=0 tile here. chunks 1..3: the copy was issued
        // during the previous chunk's kb=3 GEMM tile and has had the whole
        // eval phase to land — CP_WAIT0 below is (nearly) free.
        if (chunk == 0) {
#pragma unroll
            for (int p = 0; p < 6; p++) {
                int c  = tid + p * 512;          // 0..3071
                int jp = c >> 5;
                int co = (c & 31) * 4;           // float offset in 128-float slice
                const float* src = g_sel_p + ((size_t)jp * F_) * 2 + co;
                cpa16(sel_u32[0] + (uint32_t)(jp * SEL_LD + co) * 4u, src);
            }
            CP_COMMIT();
        }

        if (tid < CCOLS) {
            float e = 0.5f * expf(-lt[nbase + tid]);
            a_s[tid] = e;
            b_s[tid] = 0.5f - e * thr[nbase + tid];
        }

        CP_WAIT0();
        __syncthreads();

        // packed GEMM accumulators: 2 rows x 3 col-pairs
        u64 fvA[3], fvB[3];
#pragma unroll
        for (int j = 0; j < 3; j++) { fvA[j] = 0ull; fvB[j] = 0ull; }

        for (int kb = 0; kb < 4; kb++) {
            const float* cur = (kb & 1) ? sel1 : sel0;
            const uint32_t nxt_u32 = sel_u32[(kb + 1) & 1];

            // issue async copy of next tile (in flight during compute)
            if (kb < 3) {
#pragma unroll
                for (int p = 0; p < 6; p++) {
                    int c  = tid + p * 512;
                    int jp = c >> 5;
                    int co = (c & 31) * 4;
                    const float* src = g_sel_p
                        + ((size_t)(pbase + jp) * F_ + (kb + 1) * 64) * 2 + co;
                    cpa16(nxt_u32 + (uint32_t)(jp * SEL_LD + co) * 4u, src);
                }
                CP_COMMIT();
            } else if (chunk < NCHUNK - 1) {
                // kb==3 computes on sel1; sel0 is dead -> preload NEXT chunk's
                // kb=0 tile now. It lands during the eval phase.
#pragma unroll
                for (int p = 0; p < 6; p++) {
                    int c  = tid + p * 512;
                    int jp = c >> 5;
                    int co = (c & 31) * 4;
                    const float* src = g_sel_p
                        + ((size_t)(pbase + NPAIR + jp) * F_) * 2 + co;
                    cpa16(sel_u32[0] + (uint32_t)(jp * SEL_LD + co) * 4u, src);
                }
                CP_COMMIT();
            }

            // compute on current tile: 16 iterations of 4 k-steps
            const float* selc = cur + jp0 * SEL_LD;
            const float* xb0  = x_t + (kb * 64) * XT_LD + r0g;
#pragma unroll 4
            for (int kq = 0; kq < 16; kq++) {
                const int kbase = kq * 8;
                ulonglong2 q0a = *(const ulonglong2*)(selc + kbase);
                ulonglong2 q0b = *(const ulonglong2*)(selc + kbase + 4);
                ulonglong2 q1a = *(const ulonglong2*)(selc + SEL_LD + kbase);
                ulonglong2 q1b = *(const ulonglong2*)(selc + SEL_LD + kbase + 4);
                ulonglong2 q2a = *(const ulonglong2*)(selc + 2 * SEL_LD + kbase);
                ulonglong2 q2b = *(const ulonglong2*)(selc + 2 * SEL_LD + kbase + 4);
                const float* xk = xb0 + (kq * 4) * XT_LD;
                float2 x0 = *(const float2*)(xk);
                float2 x1 = *(const float2*)(xk + XT_LD);
                float2 x2 = *(const float2*)(xk + 2 * XT_LD);
                float2 x3 = *(const float2*)(xk + 3 * XT_LD);

                u64 xa, xb;
                xa = pkdup(x0.x); xb = pkdup(x0.y);
                fvA[0] = fma2(xa, q0a.x, fvA[0]);
                fvA[1] = fma2(xa, q1a.x, fvA[1]);
                fvA[2] = fma2(xa, q2a.x, fvA[2]);
                fvB[0] = fma2(xb, q0a.x, fvB[0]);
                fvB[1] = fma2(xb, q1a.x, fvB[1]);
                fvB[2] = fma2(xb, q2a.x, fvB[2]);
                xa = pkdup(x1.x); xb = pkdup(x1.y);
                fvA[0] = fma2(xa, q0a.y, fvA[0]);
                fvA[1] = fma2(xa, q1a.y, fvA[1]);
                fvA[2] = fma2(xa, q2a.y, fvA[2]);
                fvB[0] = fma2(xb, q0a.y, fvB[0]);
                fvB[1] = fma2(xb, q1a.y, fvB[1]);
                fvB[2] = fma2(xb, q2a.y, fvB[2]);
                xa = pkdup(x2.x); xb = pkdup(x2.y);
                fvA[0] = fma2(xa, q0b.x, fvA[0]);
                fvA[1] = fma2(xa, q1b.x, fvA[1]);
                fvA[2] = fma2(xa, q2b.x, fvA[2]);
                fvB[0] = fma2(xb, q0b.x, fvB[0]);
                fvB[1] = fma2(xb, q1b.x, fvB[1]);
                fvB[2] = fma2(xb, q2b.x, fvB[2]);
                xa = pkdup(x3.x); xb = pkdup(x3.y);
                fvA[0] = fma2(xa, q0b.y, fvA[0]);
                fvA[1] = fma2(xa, q1b.y, fvA[1]);
                fvA[2] = fma2(xa, q2b.y, fvA[2]);
                fvB[0] = fma2(xb, q0b.y, fvB[0]);
                fvB[1] = fma2(xb, q1b.y, fvB[1]);
                fvB[2] = fma2(xb, q2b.y, fvB[2]);
            }

            if (kb < 3) {
                CP_WAIT0();      // next tile landed (issued before compute)
                __syncthreads();
            }
        }

        // sparsemoid: p = saturate(a*fv + b); rows r0g..r0g+1, cols c0..c0+5
#pragma unroll
        for (int j = 0; j < 3; j++) {
            int cc = c0 + 2 * j;
            float fa0 = lo32(fvA[j]), fa1 = hi32(fvA[j]);
            float fb0 = lo32(fvB[j]), fb1 = hi32(fvB[j]);
            p_s[r0g * P_LD + cc]           = __saturatef(fmaf(a_s[cc],     fa0, b_s[cc]));
            p_s[r0g * P_LD + cc + 1]       = __saturatef(fmaf(a_s[cc + 1], fa1, b_s[cc + 1]));
            p_s[(r0g + 1) * P_LD + cc]     = __saturatef(fmaf(a_s[cc],     fb0, b_s[cc]));
            p_s[(r0g + 1) * P_LD + cc + 1] = __saturatef(fmaf(a_s[cc + 1], fb1, b_s[cc + 1]));
        }
        __syncthreads();

        // ---- tree eval: warp w handles trees chunk*32 + {w, w+16} ----
        for (int it = 0; it < 2; it++) {
            const int tloc = it * 16 + w;
            const int tg   = chunk * 32 + tloc;
            const float4* rg = (const float4*)(resp + (size_t)tg * (U_ * NB_));

            const int pc = tloc * 6;
            u64 r01p[2][4], r23p[2][4], r45p[2][4];
#pragma unroll
            for (int pr = 0; pr < 2; pr++) {
                const float* prow0 = p_s + (rb + 2 * pr) * P_LD + pc;
                const float* prow1 = prow0 + P_LD;
                u64 P0 = pk(prow0[0], prow1[0]);
                u64 P1 = pk(prow0[1], prow1[1]);
                u64 P2 = pk(prow0[2], prow1[2]);
                u64 P3 = pk(prow0[3], prow1[3]);
                u64 P4 = pk(prow0[4], prow1[4]);
                u64 P5 = pk(prow0[5], prow1[5]);
                const u64 ONE = 0x3f8000003f800000ull;
                const u64 NEG = 0xbf800000bf800000ull;
                u64 Q0 = fma2(P0, NEG, ONE);
                u64 Q1 = fma2(P1, NEG, ONE);
                u64 Q2 = fma2(P2, NEG, ONE);
                u64 Q3 = fma2(P3, NEG, ONE);
                u64 Q4 = fma2(P4, NEG, ONE);
                u64 Q5 = fma2(P5, NEG, ONE);
                r01p[pr][0] = mul2(P0, P1); r01p[pr][1] = mul2(Q0, P1);
                r01p[pr][2] = mul2(P0, Q1); r01p[pr][3] = mul2(Q0, Q1);
                r23p[pr][0] = mul2(P2, P3); r23p[pr][1] = mul2(Q2, P3);
                r23p[pr][2] = mul2(P2, Q3); r23p[pr][3] = mul2(Q2, Q3);
                r45p[pr][0] = mul2(P4, P5); r45p[pr][1] = mul2(Q4, P5);
                r45p[pr][2] = mul2(P4, Q5); r45p[pr][3] = mul2(Q4, Q5);
            }

#pragma unroll
            for (int j45 = 0; j45 < 4; j45++) {
#pragma unroll
                for (int j23 = 0; j23 < 4; j23++) {
                    u64 t2p0 = mul2(r45p[0][j45], r23p[0][j23]);
                    u64 t2p1 = mul2(r45p[1][j45], r23p[1][j23]);
                    const int cq = j45 * 4 + j23;
                    float4 rv0 = __ldg(&rg[(ub + 0) * 16 + cq]);
                    float4 rv1 = __ldg(&rg[(ub + 1) * 16 + cq]);
                    float4 rv2 = __ldg(&rg[(ub + 2) * 16 + cq]);
                    float4 rv3 = __ldg(&rg[(ub + 3) * 16 + cq]);
#pragma unroll
                    for (int j01 = 0; j01 < 4; j01++) {
                        u64 rw0 = mul2(t2p0, r01p[0][j01]);
                        u64 rw1 = mul2(t2p1, r01p[1][j01]);
                        u64 e0 = pkdup(f4get(rv0, j01));
                        u64 e1 = pkdup(f4get(rv1, j01));
                        u64 e2 = pkdup(f4get(rv2, j01));
                        u64 e3 = pkdup(f4get(rv3, j01));
                        accp[0][0] = fma2(rw0, e0, accp[0][0]);
                        accp[0][1] = fma2(rw0, e1, accp[0][1]);
                        accp[0][2] = fma2(rw0, e2, accp[0][2]);
                        accp[0][3] = fma2(rw0, e3, accp[0][3]);
                        accp[1][0] = fma2(rw1, e0, accp[1][0]);
                        accp[1][1] = fma2(rw1, e1, accp[1][1]);
                        accp[1][2] = fma2(rw1, e2, accp[1][2]);
                        accp[1][3] = fma2(rw1, e3, accp[1][3]);
                    }
                }
            }
        }
    }

    // unpack accumulators into scalars
    float acc[4][4];
#pragma unroll
    for (int pr = 0; pr < 2; pr++)
#pragma unroll
        for (int uu = 0; uu < 4; uu++) {
            acc[2 * pr + 0][uu] = lo32(accp[pr][uu]);
            acc[2 * pr + 1][uu] = hi32(accp[pr][uu]);
        }

    // deterministic cross-warp reduction into out_s
    for (int pass = 0; pass < 16; pass++) {
        __syncthreads();
        if (w == pass) {
#pragma unroll
            for (int rr = 0; rr < 4; rr++)
#pragma unroll
                for (int uu = 0; uu < 4; uu++)
                    out_s[(rb + rr) * U_ + ub + uu] += acc[rr][uu];
        }
    }
    __syncthreads();

    out[(size_t)row0 * U_ + tid] = out_s[tid];
}

// ---------------------------------------------------------------------------
extern "C" void kernel_launch(void* const* d_in, const int* in_sizes, int n_in,
                              void* d_out, int out_size) {
    const float* x    = (const float*)d_in[0];
    const float* fsl  = (const float*)d_in[1];
    const float* thr  = (const float*)d_in[2];
    const float* lt   = (const float*)d_in[3];
    const float* resp = (const float*)d_in[4];
    float* out = (float*)d_out;

    const int smem_bytes =
        (256 * XT_LD + 2 * NPAIR * SEL_LD + 32 * P_LD + 2 * CCOLS + 512)
        * (int)sizeof(float);   // 163,968 B

    cudaFuncSetAttribute(odst_main, cudaFuncAttributeMaxDynamicSharedMemorySize,
                         smem_bytes);

    sparsemax_kernel<<<(F_ * T_) / 256, 256>>>(fsl);
    odst_main<<<(4096 / BROWS), THREADS, smem_bytes>>>(x, thr, lt, resp, out);
}